// round 1
// baseline (speedup 1.0000x reference)
#include <cuda_runtime.h>
#include <cuda_bf16.h>

// ---------------- problem constants ----------------
#define BATCH 4
#define C1c   128
#define H1c   128
#define C2c   64
#define H2c   64
#define Lc    4096      // 64*64 patches / spatial positions
#define KPc   576       // C2*3*3  (x2 patch length)
#define KW1c  2048      // C1*4*4  (x1 patch length)
#define SCALEF 10.0f

// ---------------- scratch (device globals: allocation-free) ----------------
__device__ float g_P [BATCH][Lc][KPc];    // im2col(x2)                 ~37.7 MB
__device__ float g_S [BATCH][Lc][Lc];     // scores [s][l] -> yi        ~268 MB
__device__ float g_W1[BATCH][Lc][KW1c];   // im2col(x1, k4 s2)          ~134 MB
__device__ float g_Z [BATCH][Lc][KW1c];   // yi @ W1  [s][(c,u,v)]      ~134 MB
__device__ float g_norm[BATCH][Lc];
__device__ float g_mm [BATCH][Lc];
__device__ float g_y [BATCH][C1c][H1c][H1c]; // reconstructed image     ~33.5 MB

// ---------------- im2col of x2: P[b][l][c*9+kh*3+kw] ----------------
__global__ void k_im2col_P(const float* __restrict__ x2) {
    long idx = (long)blockIdx.x * blockDim.x + threadIdx.x;
    if (idx >= (long)BATCH * Lc * KPc) return;
    int k = (int)(idx % KPc);
    long t = idx / KPc;
    int l = (int)(t % Lc);
    int b = (int)(t / Lc);
    int c = k / 9, kh = (k % 9) / 3, kw = k % 3;
    int ph = l >> 6, pw = l & 63;
    int r = ph + kh - 1, cc = pw + kw - 1;
    float v = 0.f;
    if ((unsigned)r < H2c && (unsigned)cc < H2c)
        v = x2[(((long)b * C2c + c) * H2c + r) * H2c + cc];
    g_P[b][l][k] = v;
}

// ---------------- patch norms of P + mask mm ----------------
__global__ void k_norm_mm(const float* __restrict__ mask) {
    int warp = (blockIdx.x * blockDim.x + threadIdx.x) >> 5;
    int lane = threadIdx.x & 31;
    if (warp >= BATCH * Lc) return;
    int b = warp / Lc, l = warp % Lc;
    const float* row = g_P[b][l];
    float s = 0.f;
    for (int k = lane; k < KPc; k += 32) { float v = row[k]; s += v * v; }
    #pragma unroll
    for (int o = 16; o > 0; o >>= 1) s += __shfl_down_sync(0xffffffffu, s, o);
    if (lane == 0) {
        g_norm[b][l] = sqrtf(s);
        int ph = l >> 6, pw = l & 63;
        float msum = 0.f;
        for (int u = 0; u < 4; u++) {
            int r = 2 * ph - 1 + u;
            if ((unsigned)r >= H1c) continue;
            for (int v = 0; v < 4; v++) {
                int c = 2 * pw - 1 + v;
                if ((unsigned)c < H1c)
                    msum += mask[(long)b * H1c * H1c + r * H1c + c];
            }
        }
        g_mm[b][l] = (msum == 0.f) ? 1.f : 0.f;
    }
}

// ---------------- im2col of x1 (k=4, stride=2, pad=1): W1[b][l][c*16+u*4+v] ----------------
__global__ void k_im2col_W1(const float* __restrict__ x1) {
    long idx = (long)blockIdx.x * blockDim.x + threadIdx.x;
    if (idx >= (long)BATCH * Lc * KW1c) return;
    int j = (int)(idx % KW1c);
    long t = idx / KW1c;
    int l = (int)(t % Lc);
    int b = (int)(t / Lc);
    int c = j >> 4, u = (j >> 2) & 3, v = j & 3;
    int ph = l >> 6, pw = l & 63;
    int r = 2 * ph - 1 + u, cc = 2 * pw - 1 + v;
    float val = 0.f;
    if ((unsigned)r < H1c && (unsigned)cc < H1c)
        val = x1[(((long)b * C1c + c) * H1c + r) * H1c + cc];
    g_W1[b][l][j] = val;
}

// ---------------- classic 128x128x8 register-blocked SGEMM ----------------
// C[m][n] = sum_k A[m][k] * (TRANSB ? B[n][k] : B[k][n]); batched via blockIdx.z
template<bool TRANSB>
__global__ void __launch_bounds__(256) sgemm_k(
    const float* __restrict__ Abase, const float* __restrict__ Bbase,
    float* __restrict__ Cbase, int M, int N, int K,
    size_t sA, size_t sB, size_t sC)
{
    const float* A = Abase + (size_t)blockIdx.z * sA;
    const float* B = Bbase + (size_t)blockIdx.z * sB;
    float*       C = Cbase + (size_t)blockIdx.z * sC;
    __shared__ float As[8][128];
    __shared__ float Bs[8][128];
    int tid = threadIdx.x;
    int m0 = blockIdx.y * 128, n0 = blockIdx.x * 128;
    int trow = tid / 16, tcol = tid % 16;
    float acc[8][8];
    #pragma unroll
    for (int i = 0; i < 8; i++)
        #pragma unroll
        for (int j = 0; j < 8; j++) acc[i][j] = 0.f;
    int lr = tid >> 1;
    int lc = (tid & 1) * 4;
    for (int k0 = 0; k0 < K; k0 += 8) {
        float4 a = *(const float4*)(A + (size_t)(m0 + lr) * K + k0 + lc);
        As[lc + 0][lr] = a.x; As[lc + 1][lr] = a.y; As[lc + 2][lr] = a.z; As[lc + 3][lr] = a.w;
        if (TRANSB) {
            float4 bv = *(const float4*)(B + (size_t)(n0 + lr) * K + k0 + lc);
            Bs[lc + 0][lr] = bv.x; Bs[lc + 1][lr] = bv.y; Bs[lc + 2][lr] = bv.z; Bs[lc + 3][lr] = bv.w;
        } else {
            int bk = tid >> 5, bn = (tid & 31) * 4;
            *(float4*)&Bs[bk][bn] = *(const float4*)(B + (size_t)(k0 + bk) * N + n0 + bn);
        }
        __syncthreads();
        #pragma unroll
        for (int kk = 0; kk < 8; kk++) {
            float ra[8], rb[8];
            #pragma unroll
            for (int i = 0; i < 8; i++) ra[i] = As[kk][trow * 8 + i];
            #pragma unroll
            for (int j = 0; j < 8; j++) rb[j] = Bs[kk][tcol * 8 + j];
            #pragma unroll
            for (int i = 0; i < 8; i++)
                #pragma unroll
                for (int j = 0; j < 8; j++)
                    acc[i][j] = fmaf(ra[i], rb[j], acc[i][j]);
        }
        __syncthreads();
    }
    #pragma unroll
    for (int i = 0; i < 8; i++) {
        size_t row = (size_t)(m0 + trow * 8 + i) * N + n0 + tcol * 8;
        *(float4*)(C + row)     = make_float4(acc[i][0], acc[i][1], acc[i][2], acc[i][3]);
        *(float4*)(C + row + 4) = make_float4(acc[i][4], acc[i][5], acc[i][6], acc[i][7]);
    }
}

// ---------------- masked scale + softmax over l (contiguous row of S[s][*]) ----------------
__global__ void __launch_bounds__(256) k_softmax(const float* __restrict__ mask_all) {
    __shared__ float tv[Lc];     // 16 KB
    __shared__ float red[256];
    int s = blockIdx.x, b = blockIdx.y;
    int tid = threadIdx.x;
    float* Srow = g_S[b][s];
    float ma = mask_all[(long)b * Lc + s];
    float mx = -1e30f;
    for (int l = tid; l < Lc; l += 256) {
        float t = Srow[l] / fmaxf(g_norm[b][l], 1e-4f) * g_mm[b][l] * ma;
        t *= SCALEF;
        tv[l] = t;
        mx = fmaxf(mx, t);
    }
    red[tid] = mx; __syncthreads();
    for (int o = 128; o > 0; o >>= 1) {
        if (tid < o) red[tid] = fmaxf(red[tid], red[tid + o]);
        __syncthreads();
    }
    mx = red[0]; __syncthreads();
    float sum = 0.f;
    for (int l = tid; l < Lc; l += 256) {
        float e = expf(tv[l] - mx);
        tv[l] = e;
        sum += e;
    }
    red[tid] = sum; __syncthreads();
    for (int o = 128; o > 0; o >>= 1) {
        if (tid < o) red[tid] += red[tid + o];
        __syncthreads();
    }
    float inv = 1.f / red[0];
    for (int l = tid; l < Lc; l += 256)
        Srow[l] = fmaxf(tv[l] * inv * g_mm[b][l] * ma, 1e-8f);
}

// ---------------- col2im of Z (transposed-conv scatter, gather form) + /4 ----------------
__global__ void k_col2im() {
    long idx = (long)blockIdx.x * blockDim.x + threadIdx.x;
    if (idx >= (long)BATCH * C1c * H1c * H1c) return;
    int xx = (int)(idx % H1c);
    long t = idx / H1c;
    int yy = (int)(t % H1c); t /= H1c;
    int c = (int)(t % C1c);
    int b = (int)(t / C1c);
    int u0 = (yy + 1) & 1, v0 = (xx + 1) & 1;
    float acc = 0.f;
    #pragma unroll
    for (int du = 0; du < 2; du++) {
        int u = u0 + 2 * du;
        int sh2 = yy + 1 - u;                 // == 2*sh
        if (sh2 < 0 || sh2 >= 128) continue;
        int sh = sh2 >> 1;
        #pragma unroll
        for (int dv = 0; dv < 2; dv++) {
            int v = v0 + 2 * dv;
            int sw2 = xx + 1 - v;
            if (sw2 < 0 || sw2 >= 128) continue;
            int sw = sw2 >> 1;
            acc += g_Z[b][sh * 64 + sw][c * 16 + u * 4 + v];
        }
    }
    g_y[b][c][yy][xx] = 0.25f * acc;
}

// ---------------- final dilated group convs + bias + ReLU ----------------
// block = (32,8) spatial tile; blockIdx.y = g*2 + half (8 output channels each); blockIdx.z = batch
__global__ void __launch_bounds__(256) k_groupconv(
    const float* __restrict__ w, const float* __restrict__ bias, float* __restrict__ out)
{
    __shared__ float ws[8 * 1152];
    int b = blockIdx.z;
    int g = blockIdx.y >> 1, half = blockIdx.y & 1;
    int tile = blockIdx.x;
    int tx0 = (tile & 3) * 32, ty0 = (tile >> 2) * 8;
    int tx = threadIdx.x, ty = threadIdx.y;
    int tid = ty * 32 + tx;
    int r = 1 << g;                       // RATES = 1,2,4,8
    for (int i = tid; i < 8 * 1152; i += 256) {
        int oc = i / 1152, rest = i % 1152;
        ws[i] = w[(size_t)(g * 16 + half * 8 + oc) * 1152 + rest];
    }
    __syncthreads();
    int yy = ty0 + ty, xx = tx0 + tx;
    float acc[8];
    #pragma unroll
    for (int oc = 0; oc < 8; oc++) acc[oc] = 0.f;
    for (int c = 0; c < C1c; c++) {
        const float* yb = &g_y[b][c][0][0];
        #pragma unroll
        for (int kh = 0; kh < 3; kh++) {
            int row = yy + r * (kh - 1);
            if ((unsigned)row >= H1c) continue;
            #pragma unroll
            for (int kw = 0; kw < 3; kw++) {
                int col = xx + r * (kw - 1);
                if ((unsigned)col >= H1c) continue;
                float val = __ldg(&yb[row * H1c + col]);
                int widx = c * 9 + kh * 3 + kw;
                #pragma unroll
                for (int oc = 0; oc < 8; oc++)
                    acc[oc] = fmaf(val, ws[oc * 1152 + widx], acc[oc]);
            }
        }
    }
    #pragma unroll
    for (int oc = 0; oc < 8; oc++) {
        int och = g * 16 + half * 8 + oc;
        out[(((size_t)b * 64 + och) * H1c + yy) * H1c + xx] =
            fmaxf(acc[oc] + bias[och], 0.f);
    }
}

// ---------------- launch ----------------
extern "C" void kernel_launch(void* const* d_in, const int* in_sizes, int n_in,
                              void* d_out, int out_size) {
    const float* x1       = (const float*)d_in[0];
    const float* x2       = (const float*)d_in[1];
    const float* mask     = (const float*)d_in[2];
    const float* mask_all = (const float*)d_in[3];
    const float* conv_w   = (const float*)d_in[4];
    const float* conv_b   = (const float*)d_in[5];
    float* out = (float*)d_out;

    void *pP, *pS, *pW1, *pZ;
    cudaGetSymbolAddress(&pP,  g_P);
    cudaGetSymbolAddress(&pS,  g_S);
    cudaGetSymbolAddress(&pW1, g_W1);
    cudaGetSymbolAddress(&pZ,  g_Z);

    // 1) im2col of x2
    {
        long n = (long)BATCH * Lc * KPc;
        k_im2col_P<<<(unsigned)((n + 255) / 256), 256>>>(x2);
    }
    // 2) norms + mask
    {
        long threads = (long)BATCH * Lc * 32;
        k_norm_mm<<<(unsigned)((threads + 255) / 256), 256>>>(mask);
    }
    // 3) im2col of x1
    {
        long n = (long)BATCH * Lc * KW1c;
        k_im2col_W1<<<(unsigned)((n + 255) / 256), 256>>>(x1);
    }
    // 4) GEMM1: S[s][l] = P P^T   (M=N=4096, K=576)
    sgemm_k<true><<<dim3(32, 32, BATCH), 256>>>(
        (const float*)pP, (const float*)pP, (float*)pS,
        Lc, Lc, KPc,
        (size_t)Lc * KPc, (size_t)Lc * KPc, (size_t)Lc * Lc);
    // 5) masked softmax over l, in place in S
    k_softmax<<<dim3(Lc, BATCH), 256>>>(mask_all);
    // 6) GEMM2: Z[s][j] = S[s][l] * W1[l][j]  (M=4096, N=2048, K=4096)
    sgemm_k<false><<<dim3(16, 32, BATCH), 256>>>(
        (const float*)pS, (const float*)pW1, (float*)pZ,
        Lc, KW1c, Lc,
        (size_t)Lc * Lc, (size_t)Lc * KW1c, (size_t)Lc * KW1c);
    // 7) col2im -> y
    {
        long n = (long)BATCH * C1c * H1c * H1c;
        k_col2im<<<(unsigned)((n + 255) / 256), 256>>>();
    }
    // 8) final dilated group convs
    k_groupconv<<<dim3(64, 8, BATCH), dim3(32, 8)>>>(conv_w, conv_b, out);
}

// round 3
// speedup vs baseline: 2.7875x; 2.7875x over previous
#include <cuda_runtime.h>
#include <cuda_bf16.h>
#include <cstdint>

// ---------------- problem constants ----------------
#define BATCH 4
#define C1c   128
#define H1c   128
#define C2c   64
#define H2c   64
#define Lc    4096      // 64*64
#define KPc   576       // C2*3*3
#define KW1c  2048      // C1*4*4
#define SCALEF 10.0f

// GEMM tiling
#define TM 128
#define TN 128
#define KCH 32
#define STAGE_BYTES 32768   // Ahi 8K | Alo 8K | Bhi 8K | Blo 8K  (4 k-planes x 128 rows x 16B)
#define GEMM_SMEM (2 * STAGE_BYTES)

// ---------------- scratch (device globals: allocation-free) ----------------
__device__ __nv_bfloat16 g_Phi [BATCH][Lc][KPc];
__device__ __nv_bfloat16 g_Plo [BATCH][Lc][KPc];
__device__ float         g_S   [BATCH][Lc][Lc];      // logits fp32
__device__ __nv_bfloat16 g_Shi [BATCH][Lc][Lc];      // softmax probs hi
__device__ __nv_bfloat16 g_Slo [BATCH][Lc][Lc];
__device__ __nv_bfloat16 g_W1Thi[BATCH][KW1c][Lc];   // im2col(x1) transposed [j][l]
__device__ __nv_bfloat16 g_W1Tlo[BATCH][KW1c][Lc];
__device__ float         g_Z   [BATCH][Lc][KW1c];
__device__ float         g_ssq [BATCH][H2c][H2c];
__device__ float         g_norm[BATCH][Lc];
__device__ float         g_mm  [BATCH][Lc];
__device__ float         g_y   [BATCH][C1c][H1c][H1c];

// ---------------- PTX helpers (all plain sm_80-era: valid at compute_103) ----------------
__device__ __forceinline__ uint32_t smem_u32(const void* p) {
    uint32_t a;
    asm("{ .reg .u64 t; cvta.to.shared.u64 t, %1; cvt.u32.u64 %0, t; }" : "=r"(a) : "l"(p));
    return a;
}
__device__ __forceinline__ void cp16(uint32_t dst, const void* src) {
    asm volatile("cp.async.cg.shared.global [%0], [%1], 16;" :: "r"(dst), "l"(src));
}
#define CP_COMMIT() asm volatile("cp.async.commit_group;" ::: "memory")
#define CP_WAIT0()  asm volatile("cp.async.wait_group 0;" ::: "memory")

__device__ __forceinline__ void ldsm4(uint32_t* r, uint32_t addr) {
    asm volatile("ldmatrix.sync.aligned.m8n8.x4.shared.b16 {%0,%1,%2,%3}, [%4];"
        : "=r"(r[0]), "=r"(r[1]), "=r"(r[2]), "=r"(r[3]) : "r"(addr));
}
__device__ __forceinline__ void mma16816(float* c, const uint32_t* a, uint32_t b0, uint32_t b1) {
    asm volatile(
        "mma.sync.aligned.m16n8k16.row.col.f32.bf16.bf16.f32 "
        "{%0,%1,%2,%3}, {%4,%5,%6,%7}, {%8,%9}, {%0,%1,%2,%3};"
        : "+f"(c[0]), "+f"(c[1]), "+f"(c[2]), "+f"(c[3])
        : "r"(a[0]), "r"(a[1]), "r"(a[2]), "r"(a[3]), "r"(b0), "r"(b1));
}

// ---------------- split-bf16 HMMA GEMM ----------------
// C[m][n] = sum_k A[m][k]*B[n][k], A=Ahi+Alo, B=Bhi+Blo (lo*lo dropped)
__global__ void __launch_bounds__(256) gemm_hmma(
    const __nv_bfloat16* __restrict__ Ahi_, const __nv_bfloat16* __restrict__ Alo_,
    const __nv_bfloat16* __restrict__ Bhi_, const __nv_bfloat16* __restrict__ Blo_,
    float* __restrict__ C_, int N, int K,
    size_t sA, size_t sB, size_t sC)
{
    extern __shared__ char smem[];
    const int b = blockIdx.z;
    const __nv_bfloat16* Ahi = Ahi_ + (size_t)b * sA;
    const __nv_bfloat16* Alo = Alo_ + (size_t)b * sA;
    const __nv_bfloat16* Bhi = Bhi_ + (size_t)b * sB;
    const __nv_bfloat16* Blo = Blo_ + (size_t)b * sB;
    float* C = C_ + (size_t)b * sC;

    const int m0 = blockIdx.y * TM;
    const int n0 = blockIdx.x * TN;
    const int tid = threadIdx.x, lane = tid & 31, wid = tid >> 5;
    const int warp_m = wid & 3;           // 4 warps over M (32 rows each)
    const int warp_n = wid >> 2;          // 2 warps over N (64 cols each)
    const uint32_t sbase = smem_u32(smem);

    float acc[2][8][4];
    #pragma unroll
    for (int i = 0; i < 2; i++)
        #pragma unroll
        for (int j = 0; j < 8; j++)
            #pragma unroll
            for (int q = 0; q < 4; q++) acc[i][j][q] = 0.f;

    const __nv_bfloat16* srcs[4] = { Ahi, Alo, Bhi, Blo };
    const int nch = K / KCH;

    // ---- stage loader: 4 arrays x (4 planes x 128 rows x 16B) ----
    auto load_stage = [&](int st, int k0) {
        uint32_t sb = sbase + st * STAGE_BYTES;
        #pragma unroll
        for (int a = 0; a < 4; a++) {
            const __nv_bfloat16* src = srcs[a];
            const int rb = (a >= 2) ? n0 : m0;
            #pragma unroll
            for (int rep = 0; rep < 2; rep++) {
                int cid = rep * 256 + tid;        // 0..511
                int row = cid & 127, pl = cid >> 7;
                cp16(sb + a * 8192 + pl * 2048 + row * 16,
                     src + (size_t)(rb + row) * K + k0 + pl * 8);
            }
        }
    };

    load_stage(0, 0);
    CP_COMMIT();

    const int t15 = lane & 15, t16 = lane >> 4;

    for (int c = 0; c < nch; c++) {
        CP_WAIT0();
        __syncthreads();
        if (c + 1 < nch) { load_stage((c + 1) & 1, (c + 1) * KCH); CP_COMMIT(); }

        uint32_t sb = sbase + (c & 1) * STAGE_BYTES;
        #pragma unroll
        for (int ks = 0; ks < 2; ks++) {
            uint32_t pl = (uint32_t)(ks * 2 + t16) * 2048;
            // A fragments (2 m16 tiles) hi+lo
            uint32_t ahi[2][4], alo[2][4];
            uint32_t arow = (uint32_t)(warp_m * 32 + t15) * 16;
            ldsm4(ahi[0], sb +        pl + arow);
            ldsm4(ahi[1], sb +        pl + arow + 256);
            ldsm4(alo[0], sb + 8192 + pl + arow);
            ldsm4(alo[1], sb + 8192 + pl + arow + 256);
            // B fragments (8 n8 groups) hi+lo
            uint32_t bhi[8][2], blo[8][2];
            uint32_t brow = (uint32_t)(warp_n * 64 + t15) * 16;
            #pragma unroll
            for (int g2 = 0; g2 < 4; g2++) {
                uint32_t r[4];
                ldsm4(r, sb + 16384 + pl + brow + g2 * 256);
                bhi[g2 * 2 + 0][0] = r[0]; bhi[g2 * 2 + 0][1] = r[2];
                bhi[g2 * 2 + 1][0] = r[1]; bhi[g2 * 2 + 1][1] = r[3];
                ldsm4(r, sb + 24576 + pl + brow + g2 * 256);
                blo[g2 * 2 + 0][0] = r[0]; blo[g2 * 2 + 0][1] = r[2];
                blo[g2 * 2 + 1][0] = r[1]; blo[g2 * 2 + 1][1] = r[3];
            }
            #pragma unroll
            for (int mt = 0; mt < 2; mt++)
                #pragma unroll
                for (int ng = 0; ng < 8; ng++) {
                    mma16816(acc[mt][ng], ahi[mt], bhi[ng][0], bhi[ng][1]);
                    mma16816(acc[mt][ng], ahi[mt], blo[ng][0], blo[ng][1]);
                    mma16816(acc[mt][ng], alo[mt], bhi[ng][0], bhi[ng][1]);
                }
        }
        __syncthreads();
    }

    // ---- epilogue ----
    const int trow = lane >> 2, tcol = (lane & 3) * 2;
    #pragma unroll
    for (int mt = 0; mt < 2; mt++)
        #pragma unroll
        for (int ng = 0; ng < 8; ng++) {
            float* base = C + (size_t)(m0 + warp_m * 32 + mt * 16 + trow) * N
                            + n0 + warp_n * 64 + ng * 8 + tcol;
            *(float2*)base           = make_float2(acc[mt][ng][0], acc[mt][ng][1]);
            *(float2*)(base + 8 * N) = make_float2(acc[mt][ng][2], acc[mt][ng][3]);
        }
}

// ---------------- ssq image: sum over channels of x2^2 ----------------
__global__ void k_ssq(const float* __restrict__ x2) {
    int idx = blockIdx.x * blockDim.x + threadIdx.x;
    if (idx >= BATCH * H2c * H2c) return;
    int w = idx & 63, h = (idx >> 6) & 63, b = idx >> 12;
    float s = 0.f;
    for (int c = 0; c < C2c; c++) {
        float v = x2[(((long)b * C2c + c) * H2c + h) * H2c + w];
        s += v * v;
    }
    g_ssq[b][h][w] = s;
}

// ---------------- norms + mask mm ----------------
__global__ void k_norm_mm(const float* __restrict__ mask) {
    int idx = blockIdx.x * blockDim.x + threadIdx.x;
    if (idx >= BATCH * Lc) return;
    int l = idx & (Lc - 1), b = idx / Lc;
    int ph = l >> 6, pw = l & 63;
    float s = 0.f;
    for (int kh = -1; kh <= 1; kh++) {
        int r = ph + kh;
        if ((unsigned)r >= H2c) continue;
        for (int kw = -1; kw <= 1; kw++) {
            int c = pw + kw;
            if ((unsigned)c < H2c) s += g_ssq[b][r][c];
        }
    }
    g_norm[b][l] = sqrtf(s);
    float msum = 0.f;
    for (int u = 0; u < 4; u++) {
        int r = 2 * ph - 1 + u;
        if ((unsigned)r >= H1c) continue;
        for (int v = 0; v < 4; v++) {
            int c = 2 * pw - 1 + v;
            if ((unsigned)c < H1c)
                msum += mask[(long)b * H1c * H1c + r * H1c + c];
        }
    }
    g_mm[b][l] = (msum == 0.f) ? 1.f : 0.f;
}

// ---------------- im2col of x2 -> bf16 hi/lo ----------------
__global__ void k_im2col_P(const float* __restrict__ x2) {
    long idx = (long)blockIdx.x * blockDim.x + threadIdx.x;
    if (idx >= (long)BATCH * Lc * KPc) return;
    int k = (int)(idx % KPc);
    long t = idx / KPc;
    int l = (int)(t % Lc);
    int b = (int)(t / Lc);
    int c = k / 9, kh = (k % 9) / 3, kw = k % 3;
    int ph = l >> 6, pw = l & 63;
    int r = ph + kh - 1, cc = pw + kw - 1;
    float v = 0.f;
    if ((unsigned)r < H2c && (unsigned)cc < H2c)
        v = x2[(((long)b * C2c + c) * H2c + r) * H2c + cc];
    __nv_bfloat16 hi = __float2bfloat16(v);
    g_Phi[b][l][k] = hi;
    g_Plo[b][l][k] = __float2bfloat16(v - __bfloat162float(hi));
}

// ---------------- im2col of x1 (k=4,s=2,p=1) TRANSPOSED -> bf16 hi/lo ----------------
__global__ void k_im2col_W1T(const float* __restrict__ x1) {
    long idx = (long)blockIdx.x * blockDim.x + threadIdx.x;
    if (idx >= (long)BATCH * KW1c * Lc) return;
    int l = (int)(idx % Lc);
    long t = idx / Lc;
    int j = (int)(t % KW1c);
    int b = (int)(t / KW1c);
    int c = j >> 4, u = (j >> 2) & 3, v = j & 3;
    int ph = l >> 6, pw = l & 63;
    int r = 2 * ph - 1 + u, cc = 2 * pw - 1 + v;
    float val = 0.f;
    if ((unsigned)r < H1c && (unsigned)cc < H1c)
        val = x1[(((long)b * C1c + c) * H1c + r) * H1c + cc];
    __nv_bfloat16 hi = __float2bfloat16(val);
    g_W1Thi[b][j][l] = hi;
    g_W1Tlo[b][j][l] = __float2bfloat16(val - __bfloat162float(hi));
}

// ---------------- masked scale + softmax over l; emit bf16 hi/lo probs ----------------
__global__ void __launch_bounds__(256) k_softmax(const float* __restrict__ mask_all) {
    __shared__ float tv[Lc];
    __shared__ float red[256];
    int s = blockIdx.x, b = blockIdx.y;
    int tid = threadIdx.x;
    const float* Srow = g_S[b][s];
    float ma = mask_all[(long)b * Lc + s];
    float mx = -1e30f;
    for (int l = tid; l < Lc; l += 256) {
        float t = Srow[l] / fmaxf(g_norm[b][l], 1e-4f) * g_mm[b][l] * ma * SCALEF;
        tv[l] = t;
        mx = fmaxf(mx, t);
    }
    red[tid] = mx; __syncthreads();
    for (int o = 128; o > 0; o >>= 1) {
        if (tid < o) red[tid] = fmaxf(red[tid], red[tid + o]);
        __syncthreads();
    }
    mx = red[0]; __syncthreads();
    float sum = 0.f;
    for (int l = tid; l < Lc; l += 256) {
        float e = expf(tv[l] - mx);
        tv[l] = e;
        sum += e;
    }
    red[tid] = sum; __syncthreads();
    for (int o = 128; o > 0; o >>= 1) {
        if (tid < o) red[tid] += red[tid + o];
        __syncthreads();
    }
    float inv = 1.f / red[0];
    for (int l = tid; l < Lc; l += 256) {
        float p = fmaxf(tv[l] * inv * g_mm[b][l] * ma, 1e-8f);
        __nv_bfloat16 hi = __float2bfloat16(p);
        g_Shi[b][s][l] = hi;
        g_Slo[b][s][l] = __float2bfloat16(p - __bfloat162float(hi));
    }
}

// ---------------- col2im (transposed-conv gather) + /4 ----------------
__global__ void k_col2im() {
    long idx = (long)blockIdx.x * blockDim.x + threadIdx.x;
    if (idx >= (long)BATCH * C1c * H1c * H1c) return;
    int xx = (int)(idx % H1c);
    long t = idx / H1c;
    int yy = (int)(t % H1c); t /= H1c;
    int c = (int)(t % C1c);
    int b = (int)(t / C1c);
    int u0 = (yy + 1) & 1, v0 = (xx + 1) & 1;
    float acc = 0.f;
    #pragma unroll
    for (int du = 0; du < 2; du++) {
        int u = u0 + 2 * du;
        int sh2 = yy + 1 - u;
        if (sh2 < 0 || sh2 >= 128) continue;
        int sh = sh2 >> 1;
        #pragma unroll
        for (int dv = 0; dv < 2; dv++) {
            int v = v0 + 2 * dv;
            int sw2 = xx + 1 - v;
            if (sw2 < 0 || sw2 >= 128) continue;
            int sw = sw2 >> 1;
            acc += g_Z[b][sh * 64 + sw][c * 16 + u * 4 + v];
        }
    }
    g_y[b][c][yy][xx] = 0.25f * acc;
}

// ---------------- final dilated group convs + bias + ReLU ----------------
__global__ void __launch_bounds__(256) k_groupconv(
    const float* __restrict__ w, const float* __restrict__ bias, float* __restrict__ out)
{
    __shared__ float ws[8 * 1152];
    int b = blockIdx.z;
    int g = blockIdx.y >> 1, half = blockIdx.y & 1;
    int tile = blockIdx.x;
    int tx0 = (tile & 3) * 32, ty0 = (tile >> 2) * 8;
    int tx = threadIdx.x, ty = threadIdx.y;
    int tid = ty * 32 + tx;
    int r = 1 << g;
    for (int i = tid; i < 8 * 1152; i += 256) {
        int oc = i / 1152, rest = i % 1152;
        ws[i] = w[(size_t)(g * 16 + half * 8 + oc) * 1152 + rest];
    }
    __syncthreads();
    int yy = ty0 + ty, xx = tx0 + tx;
    float acc[8];
    #pragma unroll
    for (int oc = 0; oc < 8; oc++) acc[oc] = 0.f;
    for (int c = 0; c < C1c; c++) {
        const float* yb = &g_y[b][c][0][0];
        #pragma unroll
        for (int kh = 0; kh < 3; kh++) {
            int row = yy + r * (kh - 1);
            if ((unsigned)row >= H1c) continue;
            #pragma unroll
            for (int kw = 0; kw < 3; kw++) {
                int col = xx + r * (kw - 1);
                if ((unsigned)col >= H1c) continue;
                float val = __ldg(&yb[row * H1c + col]);
                int widx = c * 9 + kh * 3 + kw;
                #pragma unroll
                for (int oc = 0; oc < 8; oc++)
                    acc[oc] = fmaf(val, ws[oc * 1152 + widx], acc[oc]);
            }
        }
    }
    #pragma unroll
    for (int oc = 0; oc < 8; oc++) {
        int och = g * 16 + half * 8 + oc;
        out[(((size_t)b * 64 + och) * H1c + yy) * H1c + xx] =
            fmaxf(acc[oc] + bias[och], 0.f);
    }
}

// ---------------- launch ----------------
extern "C" void kernel_launch(void* const* d_in, const int* in_sizes, int n_in,
                              void* d_out, int out_size) {
    const float* x1       = (const float*)d_in[0];
    const float* x2       = (const float*)d_in[1];
    const float* mask     = (const float*)d_in[2];
    const float* mask_all = (const float*)d_in[3];
    const float* conv_w   = (const float*)d_in[4];
    const float* conv_b   = (const float*)d_in[5];
    float* out = (float*)d_out;

    cudaFuncSetAttribute(gemm_hmma, cudaFuncAttributeMaxDynamicSharedMemorySize, GEMM_SMEM);

    void *pPhi, *pPlo, *pS, *pShi, *pSlo, *pWhi, *pWlo, *pZ;
    cudaGetSymbolAddress(&pPhi, g_Phi);
    cudaGetSymbolAddress(&pPlo, g_Plo);
    cudaGetSymbolAddress(&pS,   g_S);
    cudaGetSymbolAddress(&pShi, g_Shi);
    cudaGetSymbolAddress(&pSlo, g_Slo);
    cudaGetSymbolAddress(&pWhi, g_W1Thi);
    cudaGetSymbolAddress(&pWlo, g_W1Tlo);
    cudaGetSymbolAddress(&pZ,   g_Z);

    // prep
    k_ssq<<<(BATCH * H2c * H2c + 255) / 256, 256>>>(x2);
    k_norm_mm<<<(BATCH * Lc + 255) / 256, 256>>>(mask);
    {
        long n = (long)BATCH * Lc * KPc;
        k_im2col_P<<<(unsigned)((n + 255) / 256), 256>>>(x2);
    }
    {
        long n = (long)BATCH * KW1c * Lc;
        k_im2col_W1T<<<(unsigned)((n + 255) / 256), 256>>>(x1);
    }
    // GEMM1: S = P P^T  (M=N=4096, K=576)
    gemm_hmma<<<dim3(Lc / TN, Lc / TM, BATCH), 256, GEMM_SMEM>>>(
        (const __nv_bfloat16*)pPhi, (const __nv_bfloat16*)pPlo,
        (const __nv_bfloat16*)pPhi, (const __nv_bfloat16*)pPlo,
        (float*)pS, Lc, KPc,
        (size_t)Lc * KPc, (size_t)Lc * KPc, (size_t)Lc * Lc);
    // softmax -> probs (bf16 hi/lo)
    k_softmax<<<dim3(Lc, BATCH), 256>>>(mask_all);
    // GEMM2: Z[s][j] = sum_l probs[s][l] * W1T[j][l]  (M=4096, N=2048, K=4096)
    gemm_hmma<<<dim3(KW1c / TN, Lc / TM, BATCH), 256, GEMM_SMEM>>>(
        (const __nv_bfloat16*)pShi, (const __nv_bfloat16*)pSlo,
        (const __nv_bfloat16*)pWhi, (const __nv_bfloat16*)pWlo,
        (float*)pZ, KW1c, Lc,
        (size_t)Lc * Lc, (size_t)KW1c * Lc, (size_t)Lc * KW1c);
    // col2im
    {
        long n = (long)BATCH * C1c * H1c * H1c;
        k_col2im<<<(unsigned)((n + 255) / 256), 256>>>();
    }
    // final group convs
    k_groupconv<<<dim3(64, 8, BATCH), dim3(32, 8)>>>(conv_w, conv_b, out);
}